// round 16
// baseline (speedup 1.0000x reference)
#include <cuda_runtime.h>

#define TPB 128
typedef unsigned long long ull;

// MULT = pi - float-eps, folded into the stage-E form.
#define MULT_F (3.141592653589793 - 1.1920928955078125e-07)

// Precomputed trig-basis bilinear tensors Ntilde (9x9, rows padded to 10 ull),
// packed f32x2:
//   [c*180 + al*10 + be]      : circuits 0..11 (A,B,C), (N_q0, N_q1)
//   [c*180 + 90 + al*10 + be] : circuits 0..11, (N_q2, N_q3)
//   [2160 + d*90 + al*10+be]  : stage-D circuits d=0..3, (N, N)
//   [2520 + al*10 + be]       : stage-E form, (N*MULT, N*MULT)
// Pad entries (be == 9) are never written and never read (zero-init).
__device__ __align__(16) ull g_N[2610];

// theta slice per circuit: A->theta[0], B->theta[3], C->theta[4], D->theta[1], E->theta[2][0]
__device__ __forceinline__ int circ_slice(int c) {
    if (c < 4)  return c;
    if (c < 8)  return 12 + (c - 4);
    if (c < 12) return 16 + (c - 8);
    if (c < 16) return 4 + (c - 12);
    return 8;
}

__device__ __forceinline__ ull pk2(float lo, float hi) {
    ull r; asm("mov.b64 %0, {%1, %2};" : "=l"(r) : "f"(lo), "f"(hi)); return r;
}
__device__ __forceinline__ void unpk2(ull v, float& lo, float& hi) {
    asm("mov.b64 {%0, %1}, %2;" : "=f"(lo), "=f"(hi) : "l"(v));
}
__device__ __forceinline__ ull ffma2(ull a, ull b, ull c) {
    ull d; asm("fma.rn.f32x2 %0, %1, %2, %3;" : "=l"(d) : "l"(a), "l"(b), "l"(c)); return d;
}
__device__ __forceinline__ ull fmul2(ull a, ull b) {
    ull d; asm("mul.rn.f32x2 %0, %1, %2;" : "=l"(d) : "l"(a), "l"(b)); return d;
}
__device__ __forceinline__ ull fadd2(ull a, ull b) {
    ull d; asm("add.rn.f32x2 %0, %1, %2;" : "=l"(d) : "l"(a), "l"(b)); return d;
}

// ---------------------------------------------------------------------------
// Build kernel: one block per circuit (grid 17, block 100).
//  Phase 1 (t<16): build the 16x16 unitary columns into smem.
//  Phase 2 (t<100): pair-basis tensor N[10][10] (4 signs) into smem.
//  Phase 3 (t<81): trig-basis transform Ntilde = (1/16) T^t N T -> global.
// ---------------------------------------------------------------------------
__global__ void build_WM(const float* __restrict__ theta) {
    const int c = blockIdx.x, t = threadIdx.x;
    __shared__ float sWr[16][16], sWi[16][16];   // [k][col]
    __shared__ float sN0[100], sN1[100], sN2[100], sN3[100];

    if (t < 16) {
        const int col = t;
        const float* w = theta + circ_slice(c) * 48;
        float sr[16], si[16];
#pragma unroll
        for (int i = 0; i < 16; i++) { sr[i] = (i == col) ? 1.f : 0.f; si[i] = 0.f; }
#pragma unroll
        for (int l = 0; l < 4; l++) {
#pragma unroll
            for (int q = 0; q < 4; q++) {
                const float phi = w[(l * 4 + q) * 3 + 0];
                const float th  = w[(l * 4 + q) * 3 + 1];
                const float om  = w[(l * 4 + q) * 3 + 2];
                float ch, sh, ca, sa, cb, sb;
                __sincosf(0.5f * th, &sh, &ch);
                __sincosf(0.5f * (phi + om), &sa, &ca);
                __sincosf(0.5f * (phi - om), &sb, &cb);
                const float u00r =  ca * ch, u00i = -sa * ch;
                const float u01r = -cb * sh, u01i = -sb * sh;
                const float u10r =  cb * sh, u10i = -sb * sh;
                const float u11r =  ca * ch, u11i =  sa * ch;
                const int mask = 8 >> q;
#pragma unroll
                for (int k = 0; k < 16; k++) {
                    if (k & mask) continue;
                    const int k1 = k | mask;
                    float ar = sr[k],  ai = si[k];
                    float br = sr[k1], bi = si[k1];
                    sr[k]  = u00r * ar - u00i * ai + u01r * br - u01i * bi;
                    si[k]  = u00r * ai + u00i * ar + u01r * bi + u01i * br;
                    sr[k1] = u10r * ar - u10i * ai + u11r * br - u11i * bi;
                    si[k1] = u10r * ai + u10i * ar + u11r * bi + u11i * br;
                }
            }
            const int r = (l % 3) + 1;
#pragma unroll
            for (int q = 0; q < 4; q++) {
                const int cm = 8 >> q;
                const int tm = 8 >> ((q + r) & 3);
#pragma unroll
                for (int k = 0; k < 16; k++) {
                    if ((k & cm) && !(k & tm)) {
                        const int k1 = k | tm;
                        float tr = sr[k], ti = si[k];
                        sr[k] = sr[k1]; si[k] = si[k1];
                        sr[k1] = tr;    si[k1] = ti;
                    }
                }
            }
        }
#pragma unroll
        for (int k = 0; k < 16; k++) { sWr[k][col] = sr[k]; sWi[k][col] = si[k]; }
    }
    __syncthreads();

    // Phase 2: pair-basis N (unordered pairs; multiplicity included)
    {
        const int PI[10] = {0,0,0,0,1,1,1,2,2,3};
        const int PJ[10] = {0,1,2,3,1,2,3,2,3,3};
        const int a = t / 10, b = t % 10;   // t < 100
        const int i0 = PI[a], i1 = PJ[a], j0 = PI[b], j1 = PJ[b];
        const int na = (i0 == i1) ? 1 : 2;
        const int nb = (j0 == j1) ? 1 : 2;
        float n0 = 0.f, n1 = 0.f, n2 = 0.f, n3 = 0.f;
        for (int ai = 0; ai < na; ai++) {
            const int A0 = ai ? i1 : i0, A1 = ai ? i0 : i1;
            for (int bi = 0; bi < nb; bi++) {
                const int B0 = bi ? j1 : j0, B1 = bi ? j0 : j1;
                const int r  = 4 * A0 + B0;
                const int cc = 4 * A1 + B1;
#pragma unroll
                for (int k = 0; k < 16; k++) {
                    const float tt = sWr[k][r] * sWr[k][cc] + sWi[k][r] * sWi[k][cc];
                    n0 += (k & 8) ? -tt : tt;
                    n1 += (k & 4) ? -tt : tt;
                    n2 += (k & 2) ? -tt : tt;
                    n3 += (k & 1) ? -tt : tt;
                }
            }
        }
        sN0[t] = n0; sN1[t] = n1; sN2[t] = n2; sN3[t] = n3;
    }
    __syncthreads();

    // Phase 3: trig-basis transform. Basis per side: {1, cos, sin} x {1, cos, sin}.
    if (t < 81) {
        // Decomposition coefficients: pA[a] = (1/4)(P0[a]·x0)(P1[a]·x1),
        // x = (1, cos, sin).
        const float P0[10][3] = {
            {1,1,0},{1,1,0},{0,0,1},{0,0,1},{1,1,0},
            {0,0,1},{0,0,1},{1,-1,0},{1,-1,0},{1,-1,0}};
        const float P1[10][3] = {
            {1,1,0},{0,0,1},{1,1,0},{0,0,1},{1,-1,0},
            {0,0,1},{1,-1,0},{1,1,0},{0,0,1},{1,-1,0}};
        const int al = t / 9, be = t % 9;
        const int a0 = al / 3, a1 = al % 3, b0 = be / 3, b1 = be % 3;
        float m0 = 0.f, m1 = 0.f, m2 = 0.f, m3 = 0.f;
#pragma unroll
        for (int a = 0; a < 10; a++) {
            const float ca = P0[a][a0] * P1[a][a1];
            if (ca == 0.f) continue;   // compile-time-ish prune is fine here
#pragma unroll
            for (int b = 0; b < 10; b++) {
                const float cb = P0[b][b0] * P1[b][b1];
                const float cc = ca * cb;
                m0 += cc * sN0[a * 10 + b];
                m1 += cc * sN1[a * 10 + b];
                m2 += cc * sN2[a * 10 + b];
                m3 += cc * sN3[a * 10 + b];
            }
        }
        const float inv16 = 1.f / 16.f;
        m0 *= inv16; m1 *= inv16; m2 *= inv16; m3 *= inv16;
        const int idx = al * 10 + be;
        if (c < 12) {
            g_N[c * 180 + idx]      = pk2(m0, m1);
            g_N[c * 180 + 90 + idx] = pk2(m2, m3);
        } else if (c < 16) {
            g_N[2160 + (c - 12) * 90 + idx] = pk2(m0, m0);
        } else {
            const float ns = m0 * (float)MULT_F;
            g_N[2520 + idx] = pk2(ns, ns);
        }
    }
    // PDL: allow the dependent (main) kernel to start scheduling.
    asm volatile("griddepcontrol.launch_dependents;" ::: "memory");
}

// ---------------------------------------------------------------------------
// Per-circuit evaluation: e = fA^T Ntilde fB, fA/fB = {1,cos,sin} x {1,cos,sin}.
// fa scalar (packed per-use); fb packed duplicated; fa[0]=fb[0]=1 exploited.
// ---------------------------------------------------------------------------
__device__ __forceinline__ void make_fab(const float* a, float* fa, ull* fb) {
    float c0, s0, c1, s1, c2, s2, c3, s3;
    __sincosf(a[0], &s0, &c0);
    __sincosf(a[1], &s1, &c1);
    __sincosf(a[2], &s2, &c2);
    __sincosf(a[3], &s3, &c3);
    fa[0] = 1.f; fa[1] = c1; fa[2] = s1; fa[3] = c0;
    fa[4] = c0 * c1; fa[5] = c0 * s1; fa[6] = s0;
    fa[7] = s0 * c1; fa[8] = s0 * s1;
    fb[0] = pk2(c3, c3);           // fB[1]
    fb[1] = pk2(s3, s3);           // fB[2]
    fb[2] = pk2(c2, c2);           // fB[3]
    const float g4 = c2 * c3, g5 = c2 * s3, g7 = s2 * c3, g8 = s2 * s3;
    fb[3] = pk2(g4, g4);
    fb[4] = pk2(g5, g5);
    fb[5] = pk2(s2, s2);           // fB[6]
    fb[6] = pk2(g7, g7);
    fb[7] = pk2(g8, g8);
}

// Inner dot of one 9-wide row (b=0 coefficient is the constant term).
__device__ __forceinline__ ull row9(const ull* __restrict__ R, const ull* fb) {
    const ulonglong2* r = (const ulonglong2*)R;
    const ulonglong2 q0 = r[0], q1 = r[1], q2 = r[2], q3 = r[3];
    const ull r8 = R[8];
    ull t0 = ffma2(q0.y, fb[0], q0.x);
    ull t1 = fmul2(q1.x, fb[1]);
    t0 = ffma2(q1.y, fb[2], t0);
    t1 = ffma2(q2.x, fb[3], t1);
    t0 = ffma2(q2.y, fb[4], t0);
    t1 = ffma2(q3.x, fb[5], t1);
    t0 = ffma2(q3.y, fb[6], t0);
    t1 = ffma2(r8,   fb[7], t1);
    return fadd2(t0, t1);
}

// 4 expvals: packed (q0,q1) rows at N[0..89], (q2,q3) at N[90..179].
__device__ __forceinline__ void runQ4(const ull* __restrict__ N, const float* a, float* o) {
    float fa[9]; ull fb[8];
    make_fab(a, fa, fb);
    ull e01 = row9(N, fb);
    ull e23 = row9(N + 90, fb);
#pragma unroll
    for (int al = 1; al < 9; al++) {
        const ull faP = pk2(fa[al], fa[al]);
        e01 = ffma2(faP, row9(N + al * 10, fb), e01);
        e23 = ffma2(faP, row9(N + 90 + al * 10, fb), e23);
    }
    float lo, hi;
    unpk2(e01, lo, hi); o[0] = lo; o[1] = hi;
    unpk2(e23, lo, hi); o[2] = lo; o[3] = hi;
}

// Single expval (duplicated-packed rows at N[0..89]).
__device__ __forceinline__ float runQ1(const ull* __restrict__ N, const float* a) {
    float fa[9]; ull fb[8];
    make_fab(a, fa, fb);
    ull e = row9(N, fb);
#pragma unroll
    for (int al = 1; al < 9; al++) {
        const ull faP = pk2(fa[al], fa[al]);
        e = ffma2(faP, row9(N + al * 10, fb), e);
    }
    float lo, hi; unpk2(e, lo, hi);
    return lo;
}

// ---------------------------------------------------------------------------
// Main kernel: block = 32-element tile, warp w = circuit w of each stage,
// lane = element. All N reads are full-warp broadcasts. (R7 skeleton + PDL)
// ---------------------------------------------------------------------------
__global__ __launch_bounds__(TPB, 8)
void vqc_warp(const float* __restrict__ x, float* __restrict__ out, int B) {
    __shared__ __align__(16) ull sN[2610];     // 20.9 KB
    __shared__ float sH[32][17];               // 2.1 KB, stride-17 pad

    const int tid = threadIdx.x;

    // x tile load first — overlaps with the (PDL) primary kernel still running.
    const int e0 = blockIdx.x * 32;
    for (int i = tid; i < 32 * 13; i += TPB) {
        const long gi = (long)e0 * 13 + i;
        if (gi < (long)B * 13) sH[i / 13][i % 13] = x[gi];
    }

    asm volatile("griddepcontrol.wait;" ::: "memory");
    {
        const float4* s1 = (const float4*)g_N;
        float4* d1 = (float4*)sN;
        for (int i = tid; i < 1305; i += TPB) d1[i] = s1[i];
    }
    __syncthreads();

    const int w = tid >> 5;   // warp = circuit index within stage
    const int e = tid & 31;   // lane  = element within tile
    float a[4], o[4];

    // Stage A angles: H = [0, x0..x12, 0, 0]; circuit w uses H[4w..4w+3]
#pragma unroll
    for (int i = 0; i < 4; i++) {
        const int j = 4 * w + i;
        a[i] = (j >= 1 && j <= 13) ? sH[e][j - 1] : 0.f;
    }
    __syncthreads();

    // Stage A
    runQ4(sN + w * 180, a, o);
#pragma unroll
    for (int i = 0; i < 4; i++) sH[e][4 * w + i] = o[i];
    __syncthreads();
#pragma unroll
    for (int i = 0; i < 4; i++) a[i] = sH[e][4 * i + w];    // transposed wiring
    __syncthreads();

    // Stage B
    runQ4(sN + (4 + w) * 180, a, o);
#pragma unroll
    for (int i = 0; i < 4; i++) sH[e][4 * w + i] = o[i];
    __syncthreads();
#pragma unroll
    for (int i = 0; i < 4; i++) a[i] = sH[e][4 * i + w];
    __syncthreads();

    // Stage C
    runQ4(sN + (8 + w) * 180, a, o);
#pragma unroll
    for (int i = 0; i < 4; i++) sH[e][4 * w + i] = o[i];
    __syncthreads();
#pragma unroll
    for (int i = 0; i < 4; i++) a[i] = sH[e][4 * i + w];
    __syncthreads();

    // Stage D: form w
    const float h4 = runQ1(sN + 2160 + w * 90, a);
    sH[e][w] = h4;
    __syncthreads();

    // Stage E: warp 0 only (MULT baked into the E form); warp-uniform branch
    if (w != 0) return;
#pragma unroll
    for (int i = 0; i < 4; i++) a[i] = sH[e][i];
    const float r = runQ1(sN + 2520, a);
    if (e0 + e < B) out[e0 + e] = r;
}

extern "C" void kernel_launch(void* const* d_in, const int* in_sizes, int n_in,
                              void* d_out, int out_size) {
    const float* x     = (const float*)d_in[0];
    const float* theta = (const float*)d_in[1];
    if (n_in >= 2 && in_sizes[0] < in_sizes[1]) {
        x     = (const float*)d_in[1];
        theta = (const float*)d_in[0];
    }
    float* out = (float*)d_out;
    const int B = out_size;

    build_WM<<<17, 100>>>(theta);

    // Secondary launch with programmatic dependent launch (overlaps with build).
    cudaLaunchConfig_t cfg = {};
    cfg.gridDim  = dim3((B + 31) / 32);
    cfg.blockDim = dim3(TPB);
    cfg.dynamicSmemBytes = 0;
    cfg.stream = 0;
    cudaLaunchAttribute attrs[1];
    attrs[0].id = cudaLaunchAttributeProgrammaticStreamSerialization;
    attrs[0].val.programmaticStreamSerializationAllowed = 1;
    cfg.attrs = attrs;
    cfg.numAttrs = 1;
    cudaLaunchKernelEx(&cfg, vqc_warp, x, out, B);
}

// round 17
// speedup vs baseline: 2.6156x; 2.6156x over previous
#include <cuda_runtime.h>

#define TPB 128
typedef unsigned long long ull;

// MULT = pi - float-eps, folded into the stage-E form.
#define MULT_F (3.141592653589793 - 1.1920928955078125e-07)

// Precomputed trig-basis bilinear tensors Ntilde (9x9, rows padded to 10 ull),
// packed f32x2:
//   [c*180 + al*10 + be]      : circuits 0..11 (A,B,C), (N_q0, N_q1)
//   [c*180 + 90 + al*10 + be] : circuits 0..11, (N_q2, N_q3)
//   [2160 + d*90 + al*10+be]  : stage-D circuits d=0..3, (N, N)
//   [2520 + al*10 + be]       : stage-E form, (N*MULT, N*MULT)
// Pad entries (be == 9) are never written and never read (zero-init).
__device__ __align__(16) ull g_N[2610];

// Tables (global const -> L1-cached loads; NO per-thread local memory).
__device__ const int   c_PI[10] = {0,0,0,0,1,1,1,2,2,3};
__device__ const int   c_PJ[10] = {0,1,2,3,1,2,3,2,3,3};
// pA[a] = (1/4)(P0[a]·x0)(P1[a]·x1), x = (1, cos, sin)
__device__ const float c_P0[10][3] = {
    {1,1,0},{1,1,0},{0,0,1},{0,0,1},{1,1,0},
    {0,0,1},{0,0,1},{1,-1,0},{1,-1,0},{1,-1,0}};
__device__ const float c_P1[10][3] = {
    {1,1,0},{0,0,1},{1,1,0},{0,0,1},{1,-1,0},
    {0,0,1},{1,-1,0},{1,1,0},{0,0,1},{1,-1,0}};

// theta slice per circuit: A->theta[0], B->theta[3], C->theta[4], D->theta[1], E->theta[2][0]
__device__ __forceinline__ int circ_slice(int c) {
    if (c < 4)  return c;
    if (c < 8)  return 12 + (c - 4);
    if (c < 12) return 16 + (c - 8);
    if (c < 16) return 4 + (c - 12);
    return 8;
}

__device__ __forceinline__ ull pk2(float lo, float hi) {
    ull r; asm("mov.b64 %0, {%1, %2};" : "=l"(r) : "f"(lo), "f"(hi)); return r;
}
__device__ __forceinline__ void unpk2(ull v, float& lo, float& hi) {
    asm("mov.b64 {%0, %1}, %2;" : "=f"(lo), "=f"(hi) : "l"(v));
}
__device__ __forceinline__ ull ffma2(ull a, ull b, ull c) {
    ull d; asm("fma.rn.f32x2 %0, %1, %2, %3;" : "=l"(d) : "l"(a), "l"(b), "l"(c)); return d;
}
__device__ __forceinline__ ull fmul2(ull a, ull b) {
    ull d; asm("mul.rn.f32x2 %0, %1, %2;" : "=l"(d) : "l"(a), "l"(b)); return d;
}
__device__ __forceinline__ ull fadd2(ull a, ull b) {
    ull d; asm("add.rn.f32x2 %0, %1, %2;" : "=l"(d) : "l"(a), "l"(b)); return d;
}

// ---------------------------------------------------------------------------
// Build kernel: one block per circuit (grid 17, block 100).
//  Phase 1 (t<16) : 16x16 unitary columns -> smem.
//  Phase 2 (t<100): pair-basis tensor N[10][10] (4 signs) -> smem.
//  Phase 3a (t<90): coefficient matrix C[a][al] -> smem.
//  Phase 3b (t<81): Ntilde[al][be] = (1/16) sum_ab C[a][al] C[b][be] N[a][b].
// ---------------------------------------------------------------------------
__global__ void build_WM(const float* __restrict__ theta) {
    const int c = blockIdx.x, t = threadIdx.x;
    __shared__ float sWr[16][16], sWi[16][16];   // [k][col]
    __shared__ float sN0[100], sN1[100], sN2[100], sN3[100];
    __shared__ float sC[90];                     // C[a][al] = sC[a*9+al]

    if (t < 16) {
        const int col = t;
        const float* w = theta + circ_slice(c) * 48;
        float sr[16], si[16];
#pragma unroll
        for (int i = 0; i < 16; i++) { sr[i] = (i == col) ? 1.f : 0.f; si[i] = 0.f; }
#pragma unroll
        for (int l = 0; l < 4; l++) {
#pragma unroll
            for (int q = 0; q < 4; q++) {
                const float phi = w[(l * 4 + q) * 3 + 0];
                const float th  = w[(l * 4 + q) * 3 + 1];
                const float om  = w[(l * 4 + q) * 3 + 2];
                float ch, sh, ca, sa, cb, sb;
                __sincosf(0.5f * th, &sh, &ch);
                __sincosf(0.5f * (phi + om), &sa, &ca);
                __sincosf(0.5f * (phi - om), &sb, &cb);
                const float u00r =  ca * ch, u00i = -sa * ch;
                const float u01r = -cb * sh, u01i = -sb * sh;
                const float u10r =  cb * sh, u10i = -sb * sh;
                const float u11r =  ca * ch, u11i =  sa * ch;
                const int mask = 8 >> q;
#pragma unroll
                for (int k = 0; k < 16; k++) {
                    if (k & mask) continue;
                    const int k1 = k | mask;
                    float ar = sr[k],  ai = si[k];
                    float br = sr[k1], bi = si[k1];
                    sr[k]  = u00r * ar - u00i * ai + u01r * br - u01i * bi;
                    si[k]  = u00r * ai + u00i * ar + u01r * bi + u01i * br;
                    sr[k1] = u10r * ar - u10i * ai + u11r * br - u11i * bi;
                    si[k1] = u10r * ai + u10i * ar + u11r * bi + u11i * br;
                }
            }
            const int r = (l % 3) + 1;
#pragma unroll
            for (int q = 0; q < 4; q++) {
                const int cm = 8 >> q;
                const int tm = 8 >> ((q + r) & 3);
#pragma unroll
                for (int k = 0; k < 16; k++) {
                    if ((k & cm) && !(k & tm)) {
                        const int k1 = k | tm;
                        float tr = sr[k], ti = si[k];
                        sr[k] = sr[k1]; si[k] = si[k1];
                        sr[k1] = tr;    si[k1] = ti;
                    }
                }
            }
        }
#pragma unroll
        for (int k = 0; k < 16; k++) { sWr[k][col] = sr[k]; sWi[k][col] = si[k]; }
    }
    // Phase 3a can fill sC before the barrier (independent of phase 1).
    if (t < 90) {
        const int a = t / 9, al = t % 9;
        sC[t] = c_P0[a][al / 3] * c_P1[a][al % 3];
    }
    __syncthreads();

    // Phase 2: pair-basis N (unordered pairs; multiplicity included)
    {
        const int a = t / 10, b = t % 10;   // t < 100
        const int i0 = c_PI[a], i1 = c_PJ[a], j0 = c_PI[b], j1 = c_PJ[b];
        const int na = (i0 == i1) ? 1 : 2;
        const int nb = (j0 == j1) ? 1 : 2;
        float n0 = 0.f, n1 = 0.f, n2 = 0.f, n3 = 0.f;
        for (int ai = 0; ai < na; ai++) {
            const int A0 = ai ? i1 : i0, A1 = ai ? i0 : i1;
            for (int bi = 0; bi < nb; bi++) {
                const int B0 = bi ? j1 : j0, B1 = bi ? j0 : j1;
                const int r  = 4 * A0 + B0;
                const int cc = 4 * A1 + B1;
#pragma unroll
                for (int k = 0; k < 16; k++) {
                    const float tt = sWr[k][r] * sWr[k][cc] + sWi[k][r] * sWi[k][cc];
                    n0 += (k & 8) ? -tt : tt;
                    n1 += (k & 4) ? -tt : tt;
                    n2 += (k & 2) ? -tt : tt;
                    n3 += (k & 1) ? -tt : tt;
                }
            }
        }
        sN0[t] = n0; sN1[t] = n1; sN2[t] = n2; sN3[t] = n3;
    }
    __syncthreads();

    // Phase 3b: rolled loops, smem reads only.
    if (t < 81) {
        const int al = t / 9, be = t % 9;
        float m0 = 0.f, m1 = 0.f, m2 = 0.f, m3 = 0.f;
        for (int a = 0; a < 10; a++) {
            const float ca = sC[a * 9 + al];
            for (int b = 0; b < 10; b++) {
                const float cc = ca * sC[b * 9 + be];
                const int ab = a * 10 + b;
                m0 += cc * sN0[ab];
                m1 += cc * sN1[ab];
                m2 += cc * sN2[ab];
                m3 += cc * sN3[ab];
            }
        }
        const float inv16 = 1.f / 16.f;
        m0 *= inv16; m1 *= inv16; m2 *= inv16; m3 *= inv16;
        const int idx = al * 10 + be;
        if (c < 12) {
            g_N[c * 180 + idx]      = pk2(m0, m1);
            g_N[c * 180 + 90 + idx] = pk2(m2, m3);
        } else if (c < 16) {
            g_N[2160 + (c - 12) * 90 + idx] = pk2(m0, m0);
        } else {
            const float ns = m0 * (float)MULT_F;
            g_N[2520 + idx] = pk2(ns, ns);
        }
    }
    // PDL: allow the dependent (main) kernel to start scheduling.
    asm volatile("griddepcontrol.launch_dependents;" ::: "memory");
}

// ---------------------------------------------------------------------------
// Per-circuit evaluation: e = fA^T Ntilde fB, fA/fB = {1,cos,sin} x {1,cos,sin}.
// fa scalar (packed per-use); fb packed duplicated; fa[0]=fb[0]=1 exploited.
// ---------------------------------------------------------------------------
__device__ __forceinline__ void make_fab(const float* a, float* fa, ull* fb) {
    float c0, s0, c1, s1, c2, s2, c3, s3;
    __sincosf(a[0], &s0, &c0);
    __sincosf(a[1], &s1, &c1);
    __sincosf(a[2], &s2, &c2);
    __sincosf(a[3], &s3, &c3);
    fa[0] = 1.f; fa[1] = c1; fa[2] = s1; fa[3] = c0;
    fa[4] = c0 * c1; fa[5] = c0 * s1; fa[6] = s0;
    fa[7] = s0 * c1; fa[8] = s0 * s1;
    fb[0] = pk2(c3, c3);           // fB[1]
    fb[1] = pk2(s3, s3);           // fB[2]
    fb[2] = pk2(c2, c2);           // fB[3]
    const float g4 = c2 * c3, g5 = c2 * s3, g7 = s2 * c3, g8 = s2 * s3;
    fb[3] = pk2(g4, g4);
    fb[4] = pk2(g5, g5);
    fb[5] = pk2(s2, s2);           // fB[6]
    fb[6] = pk2(g7, g7);
    fb[7] = pk2(g8, g8);
}

// Inner dot of one 9-wide row (b=0 coefficient is the constant term).
__device__ __forceinline__ ull row9(const ull* __restrict__ R, const ull* fb) {
    const ulonglong2* r = (const ulonglong2*)R;
    const ulonglong2 q0 = r[0], q1 = r[1], q2 = r[2], q3 = r[3];
    const ull r8 = R[8];
    ull t0 = ffma2(q0.y, fb[0], q0.x);
    ull t1 = fmul2(q1.x, fb[1]);
    t0 = ffma2(q1.y, fb[2], t0);
    t1 = ffma2(q2.x, fb[3], t1);
    t0 = ffma2(q2.y, fb[4], t0);
    t1 = ffma2(q3.x, fb[5], t1);
    t0 = ffma2(q3.y, fb[6], t0);
    t1 = ffma2(r8,   fb[7], t1);
    return fadd2(t0, t1);
}

// 4 expvals: packed (q0,q1) rows at N[0..89], (q2,q3) at N[90..179].
__device__ __forceinline__ void runQ4(const ull* __restrict__ N, const float* a, float* o) {
    float fa[9]; ull fb[8];
    make_fab(a, fa, fb);
    ull e01 = row9(N, fb);
    ull e23 = row9(N + 90, fb);
#pragma unroll
    for (int al = 1; al < 9; al++) {
        const ull faP = pk2(fa[al], fa[al]);
        e01 = ffma2(faP, row9(N + al * 10, fb), e01);
        e23 = ffma2(faP, row9(N + 90 + al * 10, fb), e23);
    }
    float lo, hi;
    unpk2(e01, lo, hi); o[0] = lo; o[1] = hi;
    unpk2(e23, lo, hi); o[2] = lo; o[3] = hi;
}

// Single expval (duplicated-packed rows at N[0..89]).
__device__ __forceinline__ float runQ1(const ull* __restrict__ N, const float* a) {
    float fa[9]; ull fb[8];
    make_fab(a, fa, fb);
    ull e = row9(N, fb);
#pragma unroll
    for (int al = 1; al < 9; al++) {
        const ull faP = pk2(fa[al], fa[al]);
        e = ffma2(faP, row9(N + al * 10, fb), e);
    }
    float lo, hi; unpk2(e, lo, hi);
    return lo;
}

// ---------------------------------------------------------------------------
// Main kernel: block = 32-element tile, warp w = circuit w of each stage,
// lane = element. All N reads are full-warp broadcasts. (R7 skeleton + PDL)
// ---------------------------------------------------------------------------
__global__ __launch_bounds__(TPB, 8)
void vqc_warp(const float* __restrict__ x, float* __restrict__ out, int B) {
    __shared__ __align__(16) ull sN[2610];     // 20.9 KB
    __shared__ float sH[32][17];               // 2.1 KB, stride-17 pad

    const int tid = threadIdx.x;

    // x tile load first — overlaps with the (PDL) primary kernel still running.
    const int e0 = blockIdx.x * 32;
    for (int i = tid; i < 32 * 13; i += TPB) {
        const long gi = (long)e0 * 13 + i;
        if (gi < (long)B * 13) sH[i / 13][i % 13] = x[gi];
    }

    asm volatile("griddepcontrol.wait;" ::: "memory");
    {
        const float4* s1 = (const float4*)g_N;
        float4* d1 = (float4*)sN;
        for (int i = tid; i < 1305; i += TPB) d1[i] = s1[i];
    }
    __syncthreads();

    const int w = tid >> 5;   // warp = circuit index within stage
    const int e = tid & 31;   // lane  = element within tile
    float a[4], o[4];

    // Stage A angles: H = [0, x0..x12, 0, 0]; circuit w uses H[4w..4w+3]
#pragma unroll
    for (int i = 0; i < 4; i++) {
        const int j = 4 * w + i;
        a[i] = (j >= 1 && j <= 13) ? sH[e][j - 1] : 0.f;
    }
    __syncthreads();

    // Stage A
    runQ4(sN + w * 180, a, o);
#pragma unroll
    for (int i = 0; i < 4; i++) sH[e][4 * w + i] = o[i];
    __syncthreads();
#pragma unroll
    for (int i = 0; i < 4; i++) a[i] = sH[e][4 * i + w];    // transposed wiring
    __syncthreads();

    // Stage B
    runQ4(sN + (4 + w) * 180, a, o);
#pragma unroll
    for (int i = 0; i < 4; i++) sH[e][4 * w + i] = o[i];
    __syncthreads();
#pragma unroll
    for (int i = 0; i < 4; i++) a[i] = sH[e][4 * i + w];
    __syncthreads();

    // Stage C
    runQ4(sN + (8 + w) * 180, a, o);
#pragma unroll
    for (int i = 0; i < 4; i++) sH[e][4 * w + i] = o[i];
    __syncthreads();
#pragma unroll
    for (int i = 0; i < 4; i++) a[i] = sH[e][4 * i + w];
    __syncthreads();

    // Stage D: form w
    const float h4 = runQ1(sN + 2160 + w * 90, a);
    sH[e][w] = h4;
    __syncthreads();

    // Stage E: warp 0 only (MULT baked into the E form); warp-uniform branch
    if (w != 0) return;
#pragma unroll
    for (int i = 0; i < 4; i++) a[i] = sH[e][i];
    const float r = runQ1(sN + 2520, a);
    if (e0 + e < B) out[e0 + e] = r;
}

extern "C" void kernel_launch(void* const* d_in, const int* in_sizes, int n_in,
                              void* d_out, int out_size) {
    const float* x     = (const float*)d_in[0];
    const float* theta = (const float*)d_in[1];
    if (n_in >= 2 && in_sizes[0] < in_sizes[1]) {
        x     = (const float*)d_in[1];
        theta = (const float*)d_in[0];
    }
    float* out = (float*)d_out;
    const int B = out_size;

    build_WM<<<17, 100>>>(theta);

    // Secondary launch with programmatic dependent launch (overlaps with build).
    cudaLaunchConfig_t cfg = {};
    cfg.gridDim  = dim3((B + 31) / 32);
    cfg.blockDim = dim3(TPB);
    cfg.dynamicSmemBytes = 0;
    cfg.stream = 0;
    cudaLaunchAttribute attrs[1];
    attrs[0].id = cudaLaunchAttributeProgrammaticStreamSerialization;
    attrs[0].val.programmaticStreamSerializationAllowed = 1;
    cfg.attrs = attrs;
    cfg.numAttrs = 1;
    cudaLaunchKernelEx(&cfg, vqc_warp, x, out, B);
}